// round 15
// baseline (speedup 1.0000x reference)
#include <cuda_runtime.h>
#include <cuda_fp16.h>
#include <cstdint>

// ---------------- problem dims ----------------
#define N_NODES 61440
#define NEDGE   491520
#define BATCH   2048
#define TT      30
#define INCH    12
#define FCF     3840
#define FCO     72
#define NTOT    (BATCH * TT)

// ---------------- PTX helpers ----------------
__device__ __forceinline__ uint32_t smem_u32(const void* p) {
    uint32_t a;
    asm("{ .reg .u64 t; cvta.to.shared.u64 t, %1; cvt.u32.u64 %0, t; }" : "=r"(a) : "l"(p));
    return a;
}
#define LDSM_X4(r0, r1, r2, r3, addr) \
    asm volatile("ldmatrix.sync.aligned.m8n8.x4.shared.b16 {%0,%1,%2,%3}, [%4];" \
        : "=r"(r0), "=r"(r1), "=r"(r2), "=r"(r3) : "r"(addr))
#define MMA_F16(acc, a, b0_, b1_) \
    asm volatile("mma.sync.aligned.m16n8k16.row.col.f32.f16.f16.f32 " \
        "{%0,%1,%2,%3}, {%4,%5,%6,%7}, {%8,%9}, {%0,%1,%2,%3};" \
        : "+f"((acc)[0]), "+f"((acc)[1]), "+f"((acc)[2]), "+f"((acc)[3]) \
        : "r"((a)[0]), "r"((a)[1]), "r"((a)[2]), "r"((a)[3]), "r"(b0_), "r"(b1_))
#define CP_ASYNC16(dst, src) \
    asm volatile("cp.async.cg.shared.global [%0], [%1], 16;" :: "r"(dst), "l"(src))
#define CP_ASYNC16Z(dst, src, sz) \
    asm volatile("cp.async.cg.shared.global [%0], [%1], 16, %2;" :: "r"(dst), "l"(src), "r"(sz))
#define CP_COMMIT() asm volatile("cp.async.commit_group;" ::: "memory")
#define CP_WAIT2()  asm volatile("cp.async.wait_group 2;" ::: "memory")
#define CP_WAIT0()  asm volatile("cp.async.wait_group 0;" ::: "memory")
#define SWZ(row, c16) (((uint32_t)(row)) * 128u + ((((uint32_t)(c16)) ^ (((uint32_t)(row)) & 7u)) << 4))
#define RED_V4(ptr, a, b, c, d) \
    asm volatile("red.global.add.v4.f32 [%0], {%1, %2, %3, %4};" \
        :: "l"(ptr), "f"(a), "f"(b), "f"(c), "f"(d) : "memory")

// ---------------- device scratch ----------------
__device__ float g_deg [N_NODES];
__device__ __align__(16) float  g_h  [N_NODES * 12];          // [node][12]
__device__ __align__(16) float  g_x0 [N_NODES * 12];          // [node][12] = sum dinv_s*h_s
__device__ __align__(16) __half g_x1h[NTOT * 128];            // [n][128] fp16
__device__ __align__(16) __half g_x2h[NTOT * 512];            // [n][512] fp16
__device__ __align__(16) __half g_x3h[NTOT * 128];            // [n][128] fp16 (== [b][k'], k'=t*128+oc)
__device__ __align__(16) __half g_fcwh[80 * FCF];             // fp16 [80 rows (72 valid)][k']
__device__ int g_eflag[1];                                    // idempotent OR, never reset

// fp16 weights
__device__ __align__(16) __half g_wc0h[128 * 64];             // block0 conv A: k = j*16+ic
__device__ __align__(16) __half g_wd0h[128 * 64];             // block0 down A: k = 32+ic only
__device__ __align__(16) __half g_wc1[512 * 384];             // [oc][k], k = j*IC+ic
__device__ __align__(16) __half g_wd1[512 * 128];
__device__ __align__(16) __half g_wc2[128 * 1536];
__device__ __align__(16) __half g_wd2[128 * 512];

__device__ __forceinline__ void load_edge(const void* ep, int e, int& s, int& d) {
    if (g_eflag[0]) {
        const int* p = (const int*)ep;
        s = p[e]; d = p[NEDGE + e];
    } else {
        const long long* p = (const long long*)ep;
        s = (int)p[e]; d = (int)p[NEDGE + e];
    }
}

// ---------------- fused init + detect + out-bias + weight prep + GCN-h (ONE launch) ----------------
#define P0 (N_NODES * 12)                 // x0 zero (+ deg=1 for i<N_NODES)
#define P1 (P0 + BATCH * FCO)             // out bias init
#define P2 (P1 + 2048)                    // dtype detect
#define Z0 (P2 + 8192)                    // wc0h
#define Z1 (Z0 + 8192)                    // wd0h
#define Q1 (Z1 + 196608)                  // wc1
#define Q2 (Q1 + 65536)                   // wd1
#define Q3 (Q2 + 196608)                  // wc2
#define Q4 (Q3 + 65536)                   // wd2
#define Q5 (Q4 + 80 * FCF)                // fcwh
#define Q6 (Q5 + N_NODES)                 // h = x @ gcn_w^T
__global__ void k_setup(const void* __restrict__ ep,
                        const float* __restrict__ fb, float* __restrict__ out,
                        const float* __restrict__ cw0, const float* __restrict__ dw0,
                        const float* __restrict__ cw1, const float* __restrict__ dw1,
                        const float* __restrict__ cw2, const float* __restrict__ dw2,
                        const float* __restrict__ fw,
                        const float* __restrict__ x, const float* __restrict__ gw) {
    int id = blockIdx.x * blockDim.x + threadIdx.x;
    if (id < P0) {
        g_x0[id] = 0.0f;
        if (id < N_NODES) g_deg[id] = 1.0f;
    } else if (id < P1) {
        int i = id - P0;
        out[i] = fb[i % FCO];
    } else if (id < P2) {
        int i = id - P1;
        long long v = ((const long long*)ep)[i];
        if (v < 0 || v >= N_NODES) atomicOr(g_eflag, 1);
    } else if (id < Z0) {
        int t = id - P2;            // wc0h: [oc][64], k=j*16+ic
        int oc = t >> 6, k = t & 63;
        int j = k >> 4, ic = k & 15;
        float v = (j < 3 && ic < 12) ? cw0[(oc * 12 + ic) * 3 + j] : 0.0f;
        g_wc0h[t] = __float2half_rn(v);
    } else if (id < Z1) {
        int t = id - Z0;            // wd0h: wd at k=32+ic only
        int oc = t >> 6, k = t & 63;
        int j = k >> 4, ic = k & 15;
        float v = (j == 2 && ic < 12) ? dw0[oc * 12 + ic] : 0.0f;
        g_wd0h[t] = __float2half_rn(v);
    } else if (id < Q1) {
        int t = id - Z1;
        int oc = t / 384, r = t % 384, j = r / 128, ic = r % 128;
        g_wc1[t] = __float2half_rn(cw1[(oc * 128 + ic) * 3 + j]);
    } else if (id < Q2) {
        int t = id - Q1;
        g_wd1[t] = __float2half_rn(dw1[t]);
    } else if (id < Q3) {
        int t = id - Q2;
        int oc = t / 1536, r = t % 1536, j = r / 512, ic = r % 512;
        g_wc2[t] = __float2half_rn(cw2[(oc * 512 + ic) * 3 + j]);
    } else if (id < Q4) {
        int t = id - Q3;
        g_wd2[t] = __float2half_rn(dw2[t]);
    } else if (id < Q5) {
        int t  = id - Q4;       // [o_row][k'], k' = tt*128 + oc; src f = oc*30 + tt
        int kp = t % FCF;
        int o  = t / FCF;
        int oc = kp % 128;
        int tt = kp / 128;
        g_fcwh[t] = (o < FCO) ? __float2half_rn(fw[o * FCF + oc * 30 + tt])
                              : __half(0.0f);
    } else if (id < Q6) {
        int n = id - Q5;        // h[n][12] = x[n] @ gw^T (deg-independent)
        const float4* xp = (const float4*)(x + (size_t)n * 12);
        float4 a = xp[0], b = xp[1], c = xp[2];
        float xv[12] = {a.x,a.y,a.z,a.w, b.x,b.y,b.z,b.w, c.x,c.y,c.z,c.w};
        #pragma unroll
        for (int o = 0; o < 12; ++o) {
            float acc = 0.0f;
            #pragma unroll
            for (int i = 0; i < 12; ++i)
                acc = fmaf(xv[i], __ldg(&gw[o * 12 + i]), acc);
            g_h[n * 12 + o] = acc;
        }
    }
}

// ---------------- GCN edge kernels ----------------
__global__ void k_deg(const void* __restrict__ ep) {
    int t = blockIdx.x * blockDim.x + threadIdx.x;
    if (t * 4 >= NEDGE) return;
    int d0, d1, d2, d3;
    if (g_eflag[0]) {
        const int4* p = (const int4*)((const int*)ep + NEDGE);
        int4 v = p[t];
        d0 = v.x; d1 = v.y; d2 = v.z; d3 = v.w;
    } else {
        const longlong2* p = (const longlong2*)((const long long*)ep + NEDGE);
        longlong2 a = p[2 * t], b = p[2 * t + 1];
        d0 = (int)a.x; d1 = (int)a.y; d2 = (int)b.x; d3 = (int)b.y;
    }
    atomicAdd(&g_deg[d0], 1.0f);
    atomicAdd(&g_deg[d1], 1.0f);
    atomicAdd(&g_deg[d2], 1.0f);
    atomicAdd(&g_deg[d3], 1.0f);
}

__global__ void k_scatter(const void* __restrict__ ep) {
    int e0 = (blockIdx.x * blockDim.x + threadIdx.x) * 2;
    if (e0 >= NEDGE) return;
    int s0, d0, s1, d1;
    load_edge(ep, e0,     s0, d0);
    load_edge(ep, e0 + 1, s1, d1);
    float nm0 = rsqrtf(g_deg[s0]);
    float nm1 = rsqrtf(g_deg[s1]);
    const float4* hp0 = (const float4*)(g_h + (size_t)s0 * 12);
    const float4* hp1 = (const float4*)(g_h + (size_t)s1 * 12);
    float4 a0 = hp0[0], b0 = hp0[1], c0 = hp0[2];
    float4 a1 = hp1[0], b1 = hp1[1], c1 = hp1[2];
    float* base0 = g_x0 + (size_t)d0 * 12;
    float* base1 = g_x0 + (size_t)d1 * 12;
    RED_V4(base0,     nm0 * a0.x, nm0 * a0.y, nm0 * a0.z, nm0 * a0.w);
    RED_V4(base0 + 4, nm0 * b0.x, nm0 * b0.y, nm0 * b0.z, nm0 * b0.w);
    RED_V4(base0 + 8, nm0 * c0.x, nm0 * c0.y, nm0 * c0.z, nm0 * c0.w);
    RED_V4(base1,     nm1 * a1.x, nm1 * a1.y, nm1 * a1.z, nm1 * a1.w);
    RED_V4(base1 + 4, nm1 * b1.x, nm1 * b1.y, nm1 * b1.z, nm1 * b1.w);
    RED_V4(base1 + 8, nm1 * c1.x, nm1 * c1.y, nm1 * c1.z, nm1 * c1.w);
}

// ---------------- block 0: MMA GEMM with in-kernel GCN finalize ----------------
// A_conv has w0/w1/w2 in j-blocks (k=j*16+ic); A_down has wd in j=2 block only.
// Stage 1: finalize nodes n0-2..n0+127 into smem finBuf[130][16] fp16.
// Stage 2: B tile built from finBuf via LDS.128/STS.128 (im2col = row shift).
#define T0_OFF_AD 16384u
#define T0_OFF_B  32768u
#define T0_FIN    49152u
#define T0_AUX    66048u
#define T0_SMEM   (66048 + 1024)
__global__ __launch_bounds__(256, 1)
void tcn0_mma_kernel(const float* __restrict__ gb,
                     const __half* __restrict__ Wc, const __half* __restrict__ Wd,
                     const float* __restrict__ cb, const float* __restrict__ db,
                     __half* __restrict__ Xout) {
    extern __shared__ char smem[];
    const uint32_t sb = smem_u32(smem);
    const int tid  = threadIdx.x;
    const int wid  = tid >> 5;
    const int lane = tid & 31;
    const int n0 = blockIdx.x * 128;

    __half* finBuf = (__half*)(smem + T0_FIN);  // [130][16]
    float* bcS = (float*)(smem + T0_AUX);
    float* bdS = (float*)(smem + T0_AUX + 512);
    if (tid < 128) {
        bcS[tid] = cb[tid];
        bdS[tid] = db[tid];
    }

    const int frow = tid >> 3;   // 0..31 (+32*r2)
    const int fc16 = tid & 7;

    // A weight fills (async, overlap with finalize)
    {
        const __half* Wp  = Wc + fc16 * 8;
        const __half* Wdp = Wd + fc16 * 8;
        #pragma unroll
        for (int r2 = 0; r2 < 4; ++r2) {
            int row = frow + r2 * 32;
            uint32_t so = SWZ(row, fc16);
            CP_ASYNC16(sb + so,             Wp  + (size_t)row * 64);
            CP_ASYNC16(sb + T0_OFF_AD + so, Wdp + (size_t)row * 64);
        }
    }
    CP_COMMIT();

    // stage 1: GCN finalize into finBuf
    if (tid < 130) {
        int node = n0 - 2 + tid;
        __half hv[16];
        if (node >= 0) {
            float di = rsqrtf(g_deg[node]);
            const float4* xp = (const float4*)(g_x0 + (size_t)node * 12);
            const float4* hp = (const float4*)(g_h + (size_t)node * 12);
            #pragma unroll
            for (int q = 0; q < 3; ++q) {
                float4 xv = xp[q], hh = hp[q];
                const float* xf = (const float*)&xv;
                const float* hf = (const float*)&hh;
                #pragma unroll
                for (int c = 0; c < 4; ++c) {
                    int ic = q * 4 + c;
                    hv[ic] = __float2half_rn(di * (xf[c] + di * hf[c]) + __ldg(&gb[ic]));
                }
            }
        } else {
            #pragma unroll
            for (int c = 0; c < 12; ++c) hv[c] = __half(0.0f);
        }
        #pragma unroll
        for (int c = 12; c < 16; ++c) hv[c] = __half(0.0f);
        *(float4*)(finBuf + tid * 16)     = ((const float4*)hv)[0];
        *(float4*)(finBuf + tid * 16 + 8) = ((const float4*)hv)[1];
    }
    __syncthreads();

    // stage 2: build B tile from finBuf (chunk = finBuf[row+j], valid iff tsrc>=0)
    {
        const int j = fc16 >> 1;
        const int icHalf = (fc16 & 1) * 8;
        #pragma unroll
        for (int r2 = 0; r2 < 4; ++r2) {
            int row = frow + r2 * 32;
            uint4 val = make_uint4(0, 0, 0, 0);
            if (j < 3) {
                int tt = (n0 + row) % 30;
                if (tt - (2 - j) >= 0)
                    val = *(const uint4*)(finBuf + (row + j) * 16 + icHalf);
            }
            *(uint4*)(smem + T0_OFF_B + SWZ(row, fc16)) = val;
        }
    }
    CP_WAIT0();
    __syncthreads();

    float accC[2][8][4], accD[2][8][4];
    #pragma unroll
    for (int i = 0; i < 2; ++i)
        #pragma unroll
        for (int j = 0; j < 8; ++j)
            #pragma unroll
            for (int r = 0; r < 4; ++r) { accC[i][j][r] = 0.0f; accD[i][j][r] = 0.0f; }

    const int warpM = wid & 3;
    const int warpN = wid >> 2;
    const int arL = lane & 15;
    const int acL = lane >> 4;
    const int brL = (lane & 7) + ((lane >> 4) << 3);
    const int bcL = (lane >> 3) & 1;

    #pragma unroll
    for (int ks = 0; ks < 4; ++ks) {
        uint32_t aq[2][4], dq[2][4];
        #pragma unroll
        for (int fm = 0; fm < 2; ++fm) {
            int r = warpM * 32 + fm * 16 + arL;
            uint32_t ad = sb + SWZ(r, ks * 2 + acL);
            LDSM_X4(aq[fm][0], aq[fm][1], aq[fm][2], aq[fm][3], ad);
            LDSM_X4(dq[fm][0], dq[fm][1], dq[fm][2], dq[fm][3], ad + T0_OFF_AD);
        }
        uint32_t bq[4][4];
        #pragma unroll
        for (int gn = 0; gn < 4; ++gn) {
            int r = warpN * 64 + gn * 16 + brL;
            uint32_t bd_ = sb + T0_OFF_B + SWZ(r, ks * 2 + bcL);
            LDSM_X4(bq[gn][0], bq[gn][1], bq[gn][2], bq[gn][3], bd_);
        }
        #pragma unroll
        for (int fm = 0; fm < 2; ++fm)
            #pragma unroll
            for (int gn = 0; gn < 4; ++gn) {
                MMA_F16(accC[fm][2 * gn],     aq[fm], bq[gn][0], bq[gn][1]);
                MMA_F16(accC[fm][2 * gn + 1], aq[fm], bq[gn][2], bq[gn][3]);
                MMA_F16(accD[fm][2 * gn],     dq[fm], bq[gn][0], bq[gn][1]);
                MMA_F16(accD[fm][2 * gn + 1], dq[fm], bq[gn][2], bq[gn][3]);
            }
    }

    __syncthreads();
    float* resBuf = (float*)smem;  // [128 n][129 pitch]
    #pragma unroll
    for (int fm = 0; fm < 2; ++fm) {
        int mloc = warpM * 32 + fm * 16 + (lane >> 2);
        #pragma unroll
        for (int fn = 0; fn < 8; ++fn) {
            int nloc = warpN * 64 + fn * 8 + ((lane & 3) << 1);
            #pragma unroll
            for (int r = 0; r < 4; ++r) {
                int m = mloc + ((r >> 1) << 3);
                int n = nloc + (r & 1);
                float c = fmaxf(accC[fm][fn][r] + bcS[m], 0.0f);
                float v = fmaxf(c + accD[fm][fn][r] + bdS[m], 0.0f);
                resBuf[n * 129 + m] = v;
            }
        }
    }
    __syncthreads();
    #pragma unroll 1
    for (int idx = tid; idx < 128 * 64; idx += 256) {
        int n = idx >> 6, op = idx & 63;
        __half2 h = __floats2half2_rn(resBuf[n * 129 + 2 * op], resBuf[n * 129 + 2 * op + 1]);
        *(__half2*)(Xout + ((size_t)(n0 + n) * 128 + 2 * op)) = h;
    }
}

// ---------------- TCN blocks 1/2: 3-stage pipelined fp16 mma GEMM ----------------
template<int IC, int DIL, int OCTOT, int NT>
__global__ __launch_bounds__(256, 1)
void tcn_mma_kernel(const __half* __restrict__ Act,
                    const __half* __restrict__ Wc, const __half* __restrict__ Wd,
                    const float* __restrict__ cb, const float* __restrict__ db,
                    __half* __restrict__ Xout) {
    extern __shared__ char smem[];
    const uint32_t sb = smem_u32(smem);
    const int tid  = threadIdx.x;
    const int wid  = tid >> 5;
    const int lane = tid & 31;

    constexpr int KC  = 3 * IC;
    constexpr int NCH = KC / 64;
    constexpr int J2  = 2 * IC / 64;
    constexpr int GN  = NT / 32;
    constexpr int FN  = NT / 16;
    constexpr uint32_t OFF_B  = 16384;
    constexpr uint32_t OFF_AD = 16384 + NT * 128;
    constexpr uint32_t STAGE  = OFF_AD + 16384;
    const uint32_t AUX = 3 * STAGE;

    const int n0    = blockIdx.x * NT;
    const int mtile = blockIdx.y;

    float* bcS = (float*)(smem + AUX);
    float* bdS = (float*)(smem + AUX + 512);
    if (tid < 128) {
        bcS[tid] = cb[mtile * 128 + tid];
        bdS[tid] = db[mtile * 128 + tid];
    }

    const int frow = tid >> 3;
    const int fc16 = tid & 7;

    auto fill = [&](int ch, int stg) {
        const uint32_t base = sb + stg * STAGE;
        const int k0 = ch * 64;
        const int j  = k0 / IC;
        const int ic0 = k0 - j * IC;
        const int shift = (2 - j) * DIL;
        {
            const __half* Wp = Wc + (size_t)(mtile * 128) * KC + k0 + fc16 * 8;
            #pragma unroll
            for (int r2 = 0; r2 < 4; ++r2) {
                int row = frow + r2 * 32;
                CP_ASYNC16(base + SWZ(row, fc16), Wp + (size_t)row * KC);
            }
        }
        {
            #pragma unroll
            for (int r2 = 0; r2 < NT / 32; ++r2) {
                int row  = frow + r2 * 32;
                int ncol = n0 + row;
                int bb   = ncol / 30;
                int tt   = ncol - bb * 30;
                int tsrc = tt - shift;
                uint32_t sz = (tsrc >= 0) ? 16u : 0u;
                int ts = tsrc >= 0 ? tsrc : 0;
                const __half* s = Act + ((size_t)(bb * 30 + ts) * IC + ic0 + fc16 * 8);
                CP_ASYNC16Z(base + OFF_B + SWZ(row, fc16), s, sz);
            }
        }
        if (ch >= J2) {
            const int kd0 = k0 - 2 * IC;
            const __half* Wp = Wd + (size_t)(mtile * 128) * IC + kd0 + fc16 * 8;
            #pragma unroll
            for (int r2 = 0; r2 < 4; ++r2) {
                int row = frow + r2 * 32;
                CP_ASYNC16(base + OFF_AD + SWZ(row, fc16), Wp + (size_t)row * IC);
            }
        }
    };

    float accC[2][FN][4], accD[2][FN][4];
    #pragma unroll
    for (int i = 0; i < 2; ++i)
        #pragma unroll
        for (int j = 0; j < FN; ++j)
            #pragma unroll
            for (int r = 0; r < 4; ++r) { accC[i][j][r] = 0.0f; accD[i][j][r] = 0.0f; }

    const int warpM = wid & 3;
    const int warpN = wid >> 2;
    const int arL = lane & 15;
    const int acL = lane >> 4;
    const int brL = (lane & 7) + ((lane >> 4) << 3);
    const int bcL = (lane >> 3) & 1;

    fill(0, 0);
    CP_COMMIT();
    if (NCH > 1) fill(1, 1);
    CP_COMMIT();

    int stg = 0;
    #pragma unroll 1
    for (int ch = 0; ch < NCH; ++ch) {
        if (ch + 2 < NCH) {
            int s2 = stg + 2; if (s2 >= 3) s2 -= 3;
            fill(ch + 2, s2);
        }
        CP_COMMIT();
        CP_WAIT2();
        __syncthreads();

        const uint32_t base = sb + stg * STAGE;
        const bool dn = (ch >= J2);

        #pragma unroll
        for (int ks = 0; ks < 4; ++ks) {
            uint32_t aq[2][4];
            #pragma unroll
            for (int fm = 0; fm < 2; ++fm) {
                int r = warpM * 32 + fm * 16 + arL;
                uint32_t ad = base + SWZ(r, ks * 2 + acL);
                LDSM_X4(aq[fm][0], aq[fm][1], aq[fm][2], aq[fm][3], ad);
            }
            uint32_t bq[GN][4];
            #pragma unroll
            for (int gn = 0; gn < GN; ++gn) {
                int r = warpN * (NT / 2) + gn * 16 + brL;
                uint32_t bd_ = base + OFF_B + SWZ(r, ks * 2 + bcL);
                LDSM_X4(bq[gn][0], bq[gn][1], bq[gn][2], bq[gn][3], bd_);
            }
            #pragma unroll
            for (int fm = 0; fm < 2; ++fm)
                #pragma unroll
                for (int gn = 0; gn < GN; ++gn) {
                    MMA_F16(accC[fm][2 * gn],     aq[fm], bq[gn][0], bq[gn][1]);
                    MMA_F16(accC[fm][2 * gn + 1], aq[fm], bq[gn][2], bq[gn][3]);
                }
            if (dn) {
                uint32_t dq[2][4];
                #pragma unroll
                for (int fm = 0; fm < 2; ++fm) {
                    int r = warpM * 32 + fm * 16 + arL;
                    uint32_t ad = base + OFF_AD + SWZ(r, ks * 2 + acL);
                    LDSM_X4(dq[fm][0], dq[fm][1], dq[fm][2], dq[fm][3], ad);
                }
                #pragma unroll
                for (int fm = 0; fm < 2; ++fm)
                    #pragma unroll
                    for (int gn = 0; gn < GN; ++gn) {
                        MMA_F16(accD[fm][2 * gn],     dq[fm], bq[gn][0], bq[gn][1]);
                        MMA_F16(accD[fm][2 * gn + 1], dq[fm], bq[gn][2], bq[gn][3]);
                    }
            }
        }
        __syncthreads();
        if (++stg == 3) stg = 0;
    }

    // ---- epilogue: regs -> smem [n][oc] -> coalesced fp16 STG ----
    float* resBuf = (float*)smem;  // [NT n][129 pitch]
    #pragma unroll
    for (int fm = 0; fm < 2; ++fm) {
        int mloc = warpM * 32 + fm * 16 + (lane >> 2);
        #pragma unroll
        for (int fn = 0; fn < FN; ++fn) {
            int nloc = warpN * (NT / 2) + fn * 8 + ((lane & 3) << 1);
            #pragma unroll
            for (int r = 0; r < 4; ++r) {
                int m = mloc + ((r >> 1) << 3);
                int n = nloc + (r & 1);
                float c = fmaxf(accC[fm][fn][r] + bcS[m], 0.0f);
                float v = fmaxf(c + accD[fm][fn][r] + bdS[m], 0.0f);
                resBuf[n * 129 + m] = v;
            }
        }
    }
    __syncthreads();
    const int ocg0 = mtile * 128;
    #pragma unroll 1
    for (int idx = tid; idx < NT * 64; idx += 256) {
        int n = idx >> 6, op = idx & 63;
        __half2 h = __floats2half2_rn(resBuf[n * 129 + 2 * op], resBuf[n * 129 + 2 * op + 1]);
        *(__half2*)(Xout + ((size_t)(n0 + n) * OCTOT + ocg0 + 2 * op)) = h;
    }
}

// ---------------- FC via fp16 MMA ----------------
#define FC_KSEG 320
__global__ __launch_bounds__(320)
void fc_mma_kernel(const __half* __restrict__ X, const __half* __restrict__ W,
                   float* __restrict__ out) {
    extern __shared__ char smem[];
    const uint32_t sb = smem_u32(smem);
    const uint32_t OFF_BX = 80 * 128;
    const int tid  = threadIdx.x;
    const int wid  = tid >> 5;
    const int lane = tid & 31;

    const int n0 = blockIdx.x * 128;
    const int kbase = blockIdx.y * FC_KSEG;

    const int warpM = wid % 5;
    const int warpN = wid / 5;
    const int arL = lane & 15;
    const int acL = lane >> 4;
    const int brL = (lane & 7) + ((lane >> 4) << 3);
    const int bcL = (lane >> 3) & 1;

    float acc[8][4];
    #pragma unroll
    for (int j = 0; j < 8; ++j)
        #pragma unroll
        for (int r = 0; r < 4; ++r) acc[j][r] = 0.0f;

    #pragma unroll 1
    for (int ch = 0; ch < 5; ++ch) {
        const int k0 = kbase + ch * 64;
        __syncthreads();
        for (int s = tid; s < 80 * 8; s += 320) {
            int row = s >> 3, c16 = s & 7;
            CP_ASYNC16(sb + SWZ(row, c16), W + (size_t)row * FCF + k0 + c16 * 8);
        }
        for (int s = tid; s < 128 * 8; s += 320) {
            int row = s >> 3, c16 = s & 7;
            CP_ASYNC16(sb + OFF_BX + SWZ(row, c16),
                       X + (size_t)(n0 + row) * FCF + k0 + c16 * 8);
        }
        CP_COMMIT();
        CP_WAIT0();
        __syncthreads();

        #pragma unroll
        for (int ks = 0; ks < 4; ++ks) {
            uint32_t aq[4];
            {
                int r = warpM * 16 + arL;
                uint32_t ad = sb + SWZ(r, ks * 2 + acL);
                LDSM_X4(aq[0], aq[1], aq[2], aq[3], ad);
            }
            uint32_t bq[4][4];
            #pragma unroll
            for (int gn = 0; gn < 4; ++gn) {
                int r = warpN * 64 + gn * 16 + brL;
                uint32_t bd_ = sb + OFF_BX + SWZ(r, ks * 2 + bcL);
                LDSM_X4(bq[gn][0], bq[gn][1], bq[gn][2], bq[gn][3], bd_);
            }
            #pragma unroll
            for (int gn = 0; gn < 4; ++gn) {
                MMA_F16(acc[2 * gn],     aq, bq[gn][0], bq[gn][1]);
                MMA_F16(acc[2 * gn + 1], aq, bq[gn][2], bq[gn][3]);
            }
        }
    }

    #pragma unroll
    for (int fn = 0; fn < 8; ++fn) {
        int nloc = warpN * 64 + fn * 8 + ((lane & 3) << 1);
        #pragma unroll
        for (int r = 0; r < 4; ++r) {
            int m = warpM * 16 + (lane >> 2) + ((r >> 1) << 3);
            int n = nloc + (r & 1);
            if (m < FCO)
                atomicAdd(&out[(size_t)(n0 + n) * FCO + m], acc[fn][r]);
        }
    }
}

// ---------------- launch ----------------
extern "C" void kernel_launch(void* const* d_in, const int* in_sizes, int n_in,
                              void* d_out, int out_size) {
    const float* x       = (const float*)d_in[0];
    const void*  eidx    = d_in[1];
    const float* gcn_w   = (const float*)d_in[2];
    const float* gcn_b   = (const float*)d_in[3];
    const float* conv_w0 = (const float*)d_in[4];
    const float* conv_b0 = (const float*)d_in[5];
    const float* down_w0 = (const float*)d_in[6];
    const float* down_b0 = (const float*)d_in[7];
    const float* conv_w1 = (const float*)d_in[8];
    const float* conv_b1 = (const float*)d_in[9];
    const float* down_w1 = (const float*)d_in[10];
    const float* down_b1 = (const float*)d_in[11];
    const float* conv_w2 = (const float*)d_in[12];
    const float* conv_b2 = (const float*)d_in[13];
    const float* down_w2 = (const float*)d_in[14];
    const float* down_b2 = (const float*)d_in[15];
    const float* fc_w    = (const float*)d_in[16];
    const float* fc_b    = (const float*)d_in[17];
    float* out = (float*)d_out;

    __half *p_x1h, *p_x2h, *p_x3h, *p_fcwh;
    cudaGetSymbolAddress((void**)&p_x1h, g_x1h);
    cudaGetSymbolAddress((void**)&p_x2h, g_x2h);
    cudaGetSymbolAddress((void**)&p_x3h, g_x3h);
    cudaGetSymbolAddress((void**)&p_fcwh, g_fcwh);
    __half *wc0, *wd0, *wc1, *wd1, *wc2, *wd2;
    cudaGetSymbolAddress((void**)&wc0, g_wc0h);
    cudaGetSymbolAddress((void**)&wd0, g_wd0h);
    cudaGetSymbolAddress((void**)&wc1, g_wc1);
    cudaGetSymbolAddress((void**)&wd1, g_wd1);
    cudaGetSymbolAddress((void**)&wc2, g_wc2);
    cudaGetSymbolAddress((void**)&wd2, g_wd2);

    const int SM1 = 3 * (16384 + 128 * 128 + 16384) + 1024;  // NT=128
    const int SM2 = 3 * (16384 + 64 * 128 + 16384) + 1024;   // NT=64
    const int SMF = 80 * 128 + 128 * 128;
    cudaFuncSetAttribute(tcn0_mma_kernel,
                         cudaFuncAttributeMaxDynamicSharedMemorySize, T0_SMEM);
    cudaFuncSetAttribute(tcn_mma_kernel<128, 3, 512, 128>,
                         cudaFuncAttributeMaxDynamicSharedMemorySize, SM1);
    cudaFuncSetAttribute(tcn_mma_kernel<512, 9, 128, 64>,
                         cudaFuncAttributeMaxDynamicSharedMemorySize, SM2);
    cudaFuncSetAttribute(fc_mma_kernel,
                         cudaFuncAttributeMaxDynamicSharedMemorySize, SMF);

    // one fused setup launch (init + detect + out bias + weight prep + GCN h)
    k_setup<<<(Q6 + 255) / 256, 256>>>(eidx, fc_b, out,
                                       conv_w0, down_w0, conv_w1, down_w1,
                                       conv_w2, down_w2, fc_w, x, gcn_w);

    k_deg<<<(NEDGE / 4 + 255) / 256, 256>>>(eidx);
    k_scatter<<<(NEDGE / 2 + 255) / 256, 256>>>(eidx);

    tcn0_mma_kernel<<<NTOT / 128, 256, T0_SMEM>>>(
        gcn_b, wc0, wd0, conv_b0, down_b0, p_x1h);
    tcn_mma_kernel<128, 3, 512, 128><<<dim3(NTOT / 128, 4), 256, SM1>>>(
        p_x1h, wc1, wd1, conv_b1, down_b1, p_x2h);
    tcn_mma_kernel<512, 9, 128, 64><<<dim3(NTOT / 64, 1), 256, SM2>>>(
        p_x2h, wc2, wd2, conv_b2, down_b2, p_x3h);

    fc_mma_kernel<<<dim3(BATCH / 128, FCF / FC_KSEG), 320, SMF>>>(p_x3h, p_fcwh, out);
}

// round 16
// speedup vs baseline: 1.0075x; 1.0075x over previous
#include <cuda_runtime.h>
#include <cuda_fp16.h>
#include <cstdint>

// ---------------- problem dims ----------------
#define N_NODES 61440
#define NEDGE   491520
#define BATCH   2048
#define TT      30
#define INCH    12
#define FCF     3840
#define FCO     72
#define NTOT    (BATCH * TT)

// ---------------- PTX helpers ----------------
__device__ __forceinline__ uint32_t smem_u32(const void* p) {
    uint32_t a;
    asm("{ .reg .u64 t; cvta.to.shared.u64 t, %1; cvt.u32.u64 %0, t; }" : "=r"(a) : "l"(p));
    return a;
}
#define LDSM_X4(r0, r1, r2, r3, addr) \
    asm volatile("ldmatrix.sync.aligned.m8n8.x4.shared.b16 {%0,%1,%2,%3}, [%4];" \
        : "=r"(r0), "=r"(r1), "=r"(r2), "=r"(r3) : "r"(addr))
#define MMA_F16(acc, a, b0_, b1_) \
    asm volatile("mma.sync.aligned.m16n8k16.row.col.f32.f16.f16.f32 " \
        "{%0,%1,%2,%3}, {%4,%5,%6,%7}, {%8,%9}, {%0,%1,%2,%3};" \
        : "+f"((acc)[0]), "+f"((acc)[1]), "+f"((acc)[2]), "+f"((acc)[3]) \
        : "r"((a)[0]), "r"((a)[1]), "r"((a)[2]), "r"((a)[3]), "r"(b0_), "r"(b1_))
#define CP_ASYNC16(dst, src) \
    asm volatile("cp.async.cg.shared.global [%0], [%1], 16;" :: "r"(dst), "l"(src))
#define CP_ASYNC16Z(dst, src, sz) \
    asm volatile("cp.async.cg.shared.global [%0], [%1], 16, %2;" :: "r"(dst), "l"(src), "r"(sz))
#define CP_COMMIT() asm volatile("cp.async.commit_group;" ::: "memory")
#define CP_WAIT2()  asm volatile("cp.async.wait_group 2;" ::: "memory")
#define CP_WAIT0()  asm volatile("cp.async.wait_group 0;" ::: "memory")
#define SWZ(row, c16) (((uint32_t)(row)) * 128u + ((((uint32_t)(c16)) ^ (((uint32_t)(row)) & 7u)) << 4))
#define RED_V4(ptr, a, b, c, d) \
    asm volatile("red.global.add.v4.f32 [%0], {%1, %2, %3, %4};" \
        :: "l"(ptr), "f"(a), "f"(b), "f"(c), "f"(d) : "memory")

// ---------------- device scratch ----------------
__device__ float g_deg [N_NODES];
__device__ __align__(16) float  g_h  [N_NODES * 12];          // [node][12]
__device__ __align__(16) float  g_x0 [N_NODES * 12];          // [node][12] = sum dinv_s*h_s
__device__ __align__(16) __half g_x1h[NTOT * 128];            // [n][128] fp16
__device__ __align__(16) __half g_x2h[NTOT * 512];            // [n][512] fp16
__device__ __align__(16) __half g_x3h[NTOT * 128];            // [n][128] fp16 (== [b][k'], k'=t*128+oc)
__device__ __align__(16) __half g_fcwh[80 * FCF];             // fp16 [80 rows (72 valid)][k']
__device__ int g_eflag[1];                                    // idempotent OR, never reset

// fp16 weights
__device__ __align__(16) __half g_wc0h[128 * 64];             // block0 conv A: k = j*16+ic
__device__ __align__(16) __half g_wd0h[128 * 64];             // block0 down A: k = 32+ic only
__device__ __align__(16) __half g_wc1[512 * 384];             // [oc][k], k = j*IC+ic
__device__ __align__(16) __half g_wd1[512 * 128];
__device__ __align__(16) __half g_wc2[128 * 1536];
__device__ __align__(16) __half g_wd2[128 * 512];

__device__ __forceinline__ void load_edge(const void* ep, int e, int& s, int& d) {
    if (g_eflag[0]) {
        const int* p = (const int*)ep;
        s = p[e]; d = p[NEDGE + e];
    } else {
        const long long* p = (const long long*)ep;
        s = (int)p[e]; d = (int)p[NEDGE + e];
    }
}

// ---------------- fused init + detect + out-bias + weight prep + GCN-h (ONE launch) ----------------
#define P0 (N_NODES * 12)                 // x0 zero (+ deg=1 for i<N_NODES)
#define P1 (P0 + BATCH * FCO)             // out bias init
#define P2 (P1 + 2048)                    // dtype detect
#define Z0 (P2 + 8192)                    // wc0h
#define Z1 (Z0 + 8192)                    // wd0h
#define Q1 (Z1 + 196608)                  // wc1
#define Q2 (Q1 + 65536)                   // wd1
#define Q3 (Q2 + 196608)                  // wc2
#define Q4 (Q3 + 65536)                   // wd2
#define Q5 (Q4 + 80 * FCF)                // fcwh
#define Q6 (Q5 + N_NODES)                 // h = x @ gcn_w^T
__global__ void k_setup(const void* __restrict__ ep,
                        const float* __restrict__ fb, float* __restrict__ out,
                        const float* __restrict__ cw0, const float* __restrict__ dw0,
                        const float* __restrict__ cw1, const float* __restrict__ dw1,
                        const float* __restrict__ cw2, const float* __restrict__ dw2,
                        const float* __restrict__ fw,
                        const float* __restrict__ x, const float* __restrict__ gw) {
    int id = blockIdx.x * blockDim.x + threadIdx.x;
    if (id < P0) {
        g_x0[id] = 0.0f;
        if (id < N_NODES) g_deg[id] = 1.0f;
    } else if (id < P1) {
        int i = id - P0;
        out[i] = fb[i % FCO];
    } else if (id < P2) {
        int i = id - P1;
        long long v = ((const long long*)ep)[i];
        if (v < 0 || v >= N_NODES) atomicOr(g_eflag, 1);
    } else if (id < Z0) {
        int t = id - P2;            // wc0h: [oc][64], k=j*16+ic
        int oc = t >> 6, k = t & 63;
        int j = k >> 4, ic = k & 15;
        float v = (j < 3 && ic < 12) ? cw0[(oc * 12 + ic) * 3 + j] : 0.0f;
        g_wc0h[t] = __float2half_rn(v);
    } else if (id < Z1) {
        int t = id - Z0;            // wd0h: wd at k=32+ic only
        int oc = t >> 6, k = t & 63;
        int j = k >> 4, ic = k & 15;
        float v = (j == 2 && ic < 12) ? dw0[oc * 12 + ic] : 0.0f;
        g_wd0h[t] = __float2half_rn(v);
    } else if (id < Q1) {
        int t = id - Z1;
        int oc = t / 384, r = t % 384, j = r / 128, ic = r % 128;
        g_wc1[t] = __float2half_rn(cw1[(oc * 128 + ic) * 3 + j]);
    } else if (id < Q2) {
        int t = id - Q1;
        g_wd1[t] = __float2half_rn(dw1[t]);
    } else if (id < Q3) {
        int t = id - Q2;
        int oc = t / 1536, r = t % 1536, j = r / 512, ic = r % 512;
        g_wc2[t] = __float2half_rn(cw2[(oc * 512 + ic) * 3 + j]);
    } else if (id < Q4) {
        int t = id - Q3;
        g_wd2[t] = __float2half_rn(dw2[t]);
    } else if (id < Q5) {
        int t  = id - Q4;       // [o_row][k'], k' = tt*128 + oc; src f = oc*30 + tt
        int kp = t % FCF;
        int o  = t / FCF;
        int oc = kp % 128;
        int tt = kp / 128;
        g_fcwh[t] = (o < FCO) ? __float2half_rn(fw[o * FCF + oc * 30 + tt])
                              : __half(0.0f);
    } else if (id < Q6) {
        int n = id - Q5;        // h[n][12] = x[n] @ gw^T (deg-independent)
        const float4* xp = (const float4*)(x + (size_t)n * 12);
        float4 a = xp[0], b = xp[1], c = xp[2];
        float xv[12] = {a.x,a.y,a.z,a.w, b.x,b.y,b.z,b.w, c.x,c.y,c.z,c.w};
        #pragma unroll
        for (int o = 0; o < 12; ++o) {
            float acc = 0.0f;
            #pragma unroll
            for (int i = 0; i < 12; ++i)
                acc = fmaf(xv[i], __ldg(&gw[o * 12 + i]), acc);
            g_h[n * 12 + o] = acc;
        }
    }
}

// ---------------- GCN edge kernels ----------------
__global__ void k_deg(const void* __restrict__ ep) {
    int t = blockIdx.x * blockDim.x + threadIdx.x;
    if (t * 4 >= NEDGE) return;
    int d0, d1, d2, d3;
    if (g_eflag[0]) {
        const int4* p = (const int4*)((const int*)ep + NEDGE);
        int4 v = p[t];
        d0 = v.x; d1 = v.y; d2 = v.z; d3 = v.w;
    } else {
        const longlong2* p = (const longlong2*)((const long long*)ep + NEDGE);
        longlong2 a = p[2 * t], b = p[2 * t + 1];
        d0 = (int)a.x; d1 = (int)a.y; d2 = (int)b.x; d3 = (int)b.y;
    }
    atomicAdd(&g_deg[d0], 1.0f);
    atomicAdd(&g_deg[d1], 1.0f);
    atomicAdd(&g_deg[d2], 1.0f);
    atomicAdd(&g_deg[d3], 1.0f);
}

__global__ void k_scatter(const void* __restrict__ ep) {
    int e0 = (blockIdx.x * blockDim.x + threadIdx.x) * 2;
    if (e0 >= NEDGE) return;
    int s0, d0, s1, d1;
    load_edge(ep, e0,     s0, d0);
    load_edge(ep, e0 + 1, s1, d1);
    float nm0 = rsqrtf(g_deg[s0]);
    float nm1 = rsqrtf(g_deg[s1]);
    const float4* hp0 = (const float4*)(g_h + (size_t)s0 * 12);
    const float4* hp1 = (const float4*)(g_h + (size_t)s1 * 12);
    float4 a0 = hp0[0], b0 = hp0[1], c0 = hp0[2];
    float4 a1 = hp1[0], b1 = hp1[1], c1 = hp1[2];
    float* base0 = g_x0 + (size_t)d0 * 12;
    float* base1 = g_x0 + (size_t)d1 * 12;
    RED_V4(base0,     nm0 * a0.x, nm0 * a0.y, nm0 * a0.z, nm0 * a0.w);
    RED_V4(base0 + 4, nm0 * b0.x, nm0 * b0.y, nm0 * b0.z, nm0 * b0.w);
    RED_V4(base0 + 8, nm0 * c0.x, nm0 * c0.y, nm0 * c0.z, nm0 * c0.w);
    RED_V4(base1,     nm1 * a1.x, nm1 * a1.y, nm1 * a1.z, nm1 * a1.w);
    RED_V4(base1 + 4, nm1 * b1.x, nm1 * b1.y, nm1 * b1.z, nm1 * b1.w);
    RED_V4(base1 + 8, nm1 * c1.x, nm1 * c1.y, nm1 * c1.z, nm1 * c1.w);
}

// ---------------- block 0: MMA GEMM (128 oc x 64 n tile, 2 CTAs/SM) ----------------
// A_conv has w0/w1/w2 in j-blocks (k=j*16+ic); A_down has wd in j=2 block only.
// Stage 1: finalize nodes n0-2..n0+63 into smem finBuf[66][16] fp16.
// Stage 2: B tile (64 rows) built from finBuf via LDS.128/STS.128.
#define T0_OFF_AD 16384u
#define T0_OFF_B  32768u
#define T0_FIN    40960u
#define T0_AUX    43264u
#define T0_SMEM   (43264 + 1024)
__global__ __launch_bounds__(256, 2)
void tcn0_mma_kernel(const float* __restrict__ gb,
                     const __half* __restrict__ Wc, const __half* __restrict__ Wd,
                     const float* __restrict__ cb, const float* __restrict__ db,
                     __half* __restrict__ Xout) {
    extern __shared__ char smem[];
    const uint32_t sb = smem_u32(smem);
    const int tid  = threadIdx.x;
    const int wid  = tid >> 5;
    const int lane = tid & 31;
    const int n0 = blockIdx.x * 64;

    __half* finBuf = (__half*)(smem + T0_FIN);  // [66][16]
    float* bcS = (float*)(smem + T0_AUX);
    float* bdS = (float*)(smem + T0_AUX + 512);
    if (tid < 128) {
        bcS[tid] = cb[tid];
        bdS[tid] = db[tid];
    }

    const int frow = tid >> 3;   // 0..31 (+32*r2)
    const int fc16 = tid & 7;

    // A weight fills (async, overlap with finalize)
    {
        const __half* Wp  = Wc + fc16 * 8;
        const __half* Wdp = Wd + fc16 * 8;
        #pragma unroll
        for (int r2 = 0; r2 < 4; ++r2) {
            int row = frow + r2 * 32;
            uint32_t so = SWZ(row, fc16);
            CP_ASYNC16(sb + so,             Wp  + (size_t)row * 64);
            CP_ASYNC16(sb + T0_OFF_AD + so, Wdp + (size_t)row * 64);
        }
    }
    CP_COMMIT();

    // stage 1: GCN finalize into finBuf (66 nodes)
    if (tid < 66) {
        int node = n0 - 2 + tid;
        __half hv[16];
        if (node >= 0) {
            float di = rsqrtf(g_deg[node]);
            const float4* xp = (const float4*)(g_x0 + (size_t)node * 12);
            const float4* hp = (const float4*)(g_h + (size_t)node * 12);
            #pragma unroll
            for (int q = 0; q < 3; ++q) {
                float4 xv = xp[q], hh = hp[q];
                const float* xf = (const float*)&xv;
                const float* hf = (const float*)&hh;
                #pragma unroll
                for (int c = 0; c < 4; ++c) {
                    int ic = q * 4 + c;
                    hv[ic] = __float2half_rn(di * (xf[c] + di * hf[c]) + __ldg(&gb[ic]));
                }
            }
        } else {
            #pragma unroll
            for (int c = 0; c < 12; ++c) hv[c] = __half(0.0f);
        }
        #pragma unroll
        for (int c = 12; c < 16; ++c) hv[c] = __half(0.0f);
        *(float4*)(finBuf + tid * 16)     = ((const float4*)hv)[0];
        *(float4*)(finBuf + tid * 16 + 8) = ((const float4*)hv)[1];
    }
    __syncthreads();

    // stage 2: build B tile (64 rows) from finBuf
    {
        const int j = fc16 >> 1;
        const int icHalf = (fc16 & 1) * 8;
        #pragma unroll
        for (int r2 = 0; r2 < 2; ++r2) {
            int row = frow + r2 * 32;
            uint4 val = make_uint4(0, 0, 0, 0);
            if (j < 3) {
                int tt = (n0 + row) % 30;
                if (tt - (2 - j) >= 0)
                    val = *(const uint4*)(finBuf + (row + j) * 16 + icHalf);
            }
            *(uint4*)(smem + T0_OFF_B + SWZ(row, fc16)) = val;
        }
    }
    CP_WAIT0();
    __syncthreads();

    float accC[2][4][4], accD[2][4][4];
    #pragma unroll
    for (int i = 0; i < 2; ++i)
        #pragma unroll
        for (int j = 0; j < 4; ++j)
            #pragma unroll
            for (int r = 0; r < 4; ++r) { accC[i][j][r] = 0.0f; accD[i][j][r] = 0.0f; }

    const int warpM = wid & 3;
    const int warpN = wid >> 2;
    const int arL = lane & 15;
    const int acL = lane >> 4;
    const int brL = (lane & 7) + ((lane >> 4) << 3);
    const int bcL = (lane >> 3) & 1;

    #pragma unroll
    for (int ks = 0; ks < 4; ++ks) {
        uint32_t aq[2][4], dq[2][4];
        #pragma unroll
        for (int fm = 0; fm < 2; ++fm) {
            int r = warpM * 32 + fm * 16 + arL;
            uint32_t ad = sb + SWZ(r, ks * 2 + acL);
            LDSM_X4(aq[fm][0], aq[fm][1], aq[fm][2], aq[fm][3], ad);
            LDSM_X4(dq[fm][0], dq[fm][1], dq[fm][2], dq[fm][3], ad + T0_OFF_AD);
        }
        uint32_t bq[2][4];
        #pragma unroll
        for (int gn = 0; gn < 2; ++gn) {
            int r = warpN * 32 + gn * 16 + brL;
            uint32_t bd_ = sb + T0_OFF_B + SWZ(r, ks * 2 + bcL);
            LDSM_X4(bq[gn][0], bq[gn][1], bq[gn][2], bq[gn][3], bd_);
        }
        #pragma unroll
        for (int fm = 0; fm < 2; ++fm)
            #pragma unroll
            for (int gn = 0; gn < 2; ++gn) {
                MMA_F16(accC[fm][2 * gn],     aq[fm], bq[gn][0], bq[gn][1]);
                MMA_F16(accC[fm][2 * gn + 1], aq[fm], bq[gn][2], bq[gn][3]);
                MMA_F16(accD[fm][2 * gn],     dq[fm], bq[gn][0], bq[gn][1]);
                MMA_F16(accD[fm][2 * gn + 1], dq[fm], bq[gn][2], bq[gn][3]);
            }
    }

    __syncthreads();
    float* resBuf = (float*)smem;  // [64 n][129 pitch] = 33 KB
    #pragma unroll
    for (int fm = 0; fm < 2; ++fm) {
        int mloc = warpM * 32 + fm * 16 + (lane >> 2);
        #pragma unroll
        for (int fn = 0; fn < 4; ++fn) {
            int nloc = warpN * 32 + fn * 8 + ((lane & 3) << 1);
            #pragma unroll
            for (int r = 0; r < 4; ++r) {
                int m = mloc + ((r >> 1) << 3);
                int n = nloc + (r & 1);
                float c = fmaxf(accC[fm][fn][r] + bcS[m], 0.0f);
                float v = fmaxf(c + accD[fm][fn][r] + bdS[m], 0.0f);
                resBuf[n * 129 + m] = v;
            }
        }
    }
    __syncthreads();
    #pragma unroll 1
    for (int idx = tid; idx < 64 * 64; idx += 256) {
        int n = idx >> 6, op = idx & 63;
        __half2 h = __floats2half2_rn(resBuf[n * 129 + 2 * op], resBuf[n * 129 + 2 * op + 1]);
        *(__half2*)(Xout + ((size_t)(n0 + n) * 128 + 2 * op)) = h;
    }
}

// ---------------- TCN blocks 1/2: 3-stage pipelined fp16 mma GEMM ----------------
template<int IC, int DIL, int OCTOT, int NT>
__global__ __launch_bounds__(256, 1)
void tcn_mma_kernel(const __half* __restrict__ Act,
                    const __half* __restrict__ Wc, const __half* __restrict__ Wd,
                    const float* __restrict__ cb, const float* __restrict__ db,
                    __half* __restrict__ Xout) {
    extern __shared__ char smem[];
    const uint32_t sb = smem_u32(smem);
    const int tid  = threadIdx.x;
    const int wid  = tid >> 5;
    const int lane = tid & 31;

    constexpr int KC  = 3 * IC;
    constexpr int NCH = KC / 64;
    constexpr int J2  = 2 * IC / 64;
    constexpr int GN  = NT / 32;
    constexpr int FN  = NT / 16;
    constexpr uint32_t OFF_B  = 16384;
    constexpr uint32_t OFF_AD = 16384 + NT * 128;
    constexpr uint32_t STAGE  = OFF_AD + 16384;
    const uint32_t AUX = 3 * STAGE;

    const int n0    = blockIdx.x * NT;
    const int mtile = blockIdx.y;

    float* bcS = (float*)(smem + AUX);
    float* bdS = (float*)(smem + AUX + 512);
    if (tid < 128) {
        bcS[tid] = cb[mtile * 128 + tid];
        bdS[tid] = db[mtile * 128 + tid];
    }

    const int frow = tid >> 3;
    const int fc16 = tid & 7;

    auto fill = [&](int ch, int stg) {
        const uint32_t base = sb + stg * STAGE;
        const int k0 = ch * 64;
        const int j  = k0 / IC;
        const int ic0 = k0 - j * IC;
        const int shift = (2 - j) * DIL;
        {
            const __half* Wp = Wc + (size_t)(mtile * 128) * KC + k0 + fc16 * 8;
            #pragma unroll
            for (int r2 = 0; r2 < 4; ++r2) {
                int row = frow + r2 * 32;
                CP_ASYNC16(base + SWZ(row, fc16), Wp + (size_t)row * KC);
            }
        }
        {
            #pragma unroll
            for (int r2 = 0; r2 < NT / 32; ++r2) {
                int row  = frow + r2 * 32;
                int ncol = n0 + row;
                int bb   = ncol / 30;
                int tt   = ncol - bb * 30;
                int tsrc = tt - shift;
                uint32_t sz = (tsrc >= 0) ? 16u : 0u;
                int ts = tsrc >= 0 ? tsrc : 0;
                const __half* s = Act + ((size_t)(bb * 30 + ts) * IC + ic0 + fc16 * 8);
                CP_ASYNC16Z(base + OFF_B + SWZ(row, fc16), s, sz);
            }
        }
        if (ch >= J2) {
            const int kd0 = k0 - 2 * IC;
            const __half* Wp = Wd + (size_t)(mtile * 128) * IC + kd0 + fc16 * 8;
            #pragma unroll
            for (int r2 = 0; r2 < 4; ++r2) {
                int row = frow + r2 * 32;
                CP_ASYNC16(base + OFF_AD + SWZ(row, fc16), Wp + (size_t)row * IC);
            }
        }
    };

    float accC[2][FN][4], accD[2][FN][4];
    #pragma unroll
    for (int i = 0; i < 2; ++i)
        #pragma unroll
        for (int j = 0; j < FN; ++j)
            #pragma unroll
            for (int r = 0; r < 4; ++r) { accC[i][j][r] = 0.0f; accD[i][j][r] = 0.0f; }

    const int warpM = wid & 3;
    const int warpN = wid >> 2;
    const int arL = lane & 15;
    const int acL = lane >> 4;
    const int brL = (lane & 7) + ((lane >> 4) << 3);
    const int bcL = (lane >> 3) & 1;

    fill(0, 0);
    CP_COMMIT();
    if (NCH > 1) fill(1, 1);
    CP_COMMIT();

    int stg = 0;
    #pragma unroll 1
    for (int ch = 0; ch < NCH; ++ch) {
        if (ch + 2 < NCH) {
            int s2 = stg + 2; if (s2 >= 3) s2 -= 3;
            fill(ch + 2, s2);
        }
        CP_COMMIT();
        CP_WAIT2();
        __syncthreads();

        const uint32_t base = sb + stg * STAGE;
        const bool dn = (ch >= J2);

        #pragma unroll
        for (int ks = 0; ks < 4; ++ks) {
            uint32_t aq[2][4];
            #pragma unroll
            for (int fm = 0; fm < 2; ++fm) {
                int r = warpM * 32 + fm * 16 + arL;
                uint32_t ad = base + SWZ(r, ks * 2 + acL);
                LDSM_X4(aq[fm][0], aq[fm][1], aq[fm][2], aq[fm][3], ad);
            }
            uint32_t bq[GN][4];
            #pragma unroll
            for (int gn = 0; gn < GN; ++gn) {
                int r = warpN * (NT / 2) + gn * 16 + brL;
                uint32_t bd_ = base + OFF_B + SWZ(r, ks * 2 + bcL);
                LDSM_X4(bq[gn][0], bq[gn][1], bq[gn][2], bq[gn][3], bd_);
            }
            #pragma unroll
            for (int fm = 0; fm < 2; ++fm)
                #pragma unroll
                for (int gn = 0; gn < GN; ++gn) {
                    MMA_F16(accC[fm][2 * gn],     aq[fm], bq[gn][0], bq[gn][1]);
                    MMA_F16(accC[fm][2 * gn + 1], aq[fm], bq[gn][2], bq[gn][3]);
                }
            if (dn) {
                uint32_t dq[2][4];
                #pragma unroll
                for (int fm = 0; fm < 2; ++fm) {
                    int r = warpM * 32 + fm * 16 + arL;
                    uint32_t ad = base + OFF_AD + SWZ(r, ks * 2 + acL);
                    LDSM_X4(dq[fm][0], dq[fm][1], dq[fm][2], dq[fm][3], ad);
                }
                #pragma unroll
                for (int fm = 0; fm < 2; ++fm)
                    #pragma unroll
                    for (int gn = 0; gn < GN; ++gn) {
                        MMA_F16(accD[fm][2 * gn],     dq[fm], bq[gn][0], bq[gn][1]);
                        MMA_F16(accD[fm][2 * gn + 1], dq[fm], bq[gn][2], bq[gn][3]);
                    }
            }
        }
        __syncthreads();
        if (++stg == 3) stg = 0;
    }

    // ---- epilogue: regs -> smem [n][oc] -> coalesced fp16 STG ----
    float* resBuf = (float*)smem;  // [NT n][129 pitch]
    #pragma unroll
    for (int fm = 0; fm < 2; ++fm) {
        int mloc = warpM * 32 + fm * 16 + (lane >> 2);
        #pragma unroll
        for (int fn = 0; fn < FN; ++fn) {
            int nloc = warpN * (NT / 2) + fn * 8 + ((lane & 3) << 1);
            #pragma unroll
            for (int r = 0; r < 4; ++r) {
                int m = mloc + ((r >> 1) << 3);
                int n = nloc + (r & 1);
                float c = fmaxf(accC[fm][fn][r] + bcS[m], 0.0f);
                float v = fmaxf(c + accD[fm][fn][r] + bdS[m], 0.0f);
                resBuf[n * 129 + m] = v;
            }
        }
    }
    __syncthreads();
    const int ocg0 = mtile * 128;
    #pragma unroll 1
    for (int idx = tid; idx < NT * 64; idx += 256) {
        int n = idx >> 6, op = idx & 63;
        __half2 h = __floats2half2_rn(resBuf[n * 129 + 2 * op], resBuf[n * 129 + 2 * op + 1]);
        *(__half2*)(Xout + ((size_t)(n0 + n) * OCTOT + ocg0 + 2 * op)) = h;
    }
}

// ---------------- FC via fp16 MMA ----------------
#define FC_KSEG 320
__global__ __launch_bounds__(320)
void fc_mma_kernel(const __half* __restrict__ X, const __half* __restrict__ W,
                   float* __restrict__ out) {
    extern __shared__ char smem[];
    const uint32_t sb = smem_u32(smem);
    const uint32_t OFF_BX = 80 * 128;
    const int tid  = threadIdx.x;
    const int wid  = tid >> 5;
    const int lane = tid & 31;

    const int n0 = blockIdx.x * 128;
    const int kbase = blockIdx.y * FC_KSEG;

    const int warpM = wid % 5;
    const int warpN = wid / 5;
    const int arL = lane & 15;
    const int acL = lane >> 4;
    const int brL = (lane & 7) + ((lane >> 4) << 3);
    const int bcL = (lane >> 3) & 1;

    float acc[8][4];
    #pragma unroll
    for (int j = 0; j < 8; ++j)
        #pragma unroll
        for (int r = 0; r < 4; ++r) acc[j][r] = 0.0f;

    #pragma unroll 1
    for (int ch = 0; ch < 5; ++ch) {
        const int k0 = kbase + ch * 64;
        __syncthreads();
        for (int s = tid; s < 80 * 8; s += 320) {
            int row = s >> 3, c16 = s & 7;
            CP_ASYNC16(sb + SWZ(row, c16), W + (size_t)row * FCF + k0 + c16 * 8);
        }
        for (int s = tid; s < 128 * 8; s += 320) {
            int row = s >> 3, c16 = s & 7;
            CP_ASYNC16(sb + OFF_BX + SWZ(row, c16),
                       X + (size_t)(n0 + row) * FCF + k0 + c16 * 8);
        }
        CP_COMMIT();
        CP_WAIT0();
        __syncthreads();

        #pragma unroll
        for (int ks = 0; ks < 4; ++ks) {
            uint32_t aq[4];
            {
                int r = warpM * 16 + arL;
                uint32_t ad = sb + SWZ(r, ks * 2 + acL);
                LDSM_X4(aq[0], aq[1], aq[2], aq[3], ad);
            }
            uint32_t bq[4][4];
            #pragma unroll
            for (int gn = 0; gn < 4; ++gn) {
                int r = warpN * 64 + gn * 16 + brL;
                uint32_t bd_ = sb + OFF_BX + SWZ(r, ks * 2 + bcL);
                LDSM_X4(bq[gn][0], bq[gn][1], bq[gn][2], bq[gn][3], bd_);
            }
            #pragma unroll
            for (int gn = 0; gn < 4; ++gn) {
                MMA_F16(acc[2 * gn],     aq, bq[gn][0], bq[gn][1]);
                MMA_F16(acc[2 * gn + 1], aq, bq[gn][2], bq[gn][3]);
            }
        }
    }

    #pragma unroll
    for (int fn = 0; fn < 8; ++fn) {
        int nloc = warpN * 64 + fn * 8 + ((lane & 3) << 1);
        #pragma unroll
        for (int r = 0; r < 4; ++r) {
            int m = warpM * 16 + (lane >> 2) + ((r >> 1) << 3);
            int n = nloc + (r & 1);
            if (m < FCO)
                atomicAdd(&out[(size_t)(n0 + n) * FCO + m], acc[fn][r]);
        }
    }
}

// ---------------- launch ----------------
extern "C" void kernel_launch(void* const* d_in, const int* in_sizes, int n_in,
                              void* d_out, int out_size) {
    const float* x       = (const float*)d_in[0];
    const void*  eidx    = d_in[1];
    const float* gcn_w   = (const float*)d_in[2];
    const float* gcn_b   = (const float*)d_in[3];
    const float* conv_w0 = (const float*)d_in[4];
    const float* conv_b0 = (const float*)d_in[5];
    const float* down_w0 = (const float*)d_in[6];
    const float* down_b0 = (const float*)d_in[7];
    const float* conv_w1 = (const float*)d_in[8];
    const float* conv_b1 = (const float*)d_in[9];
    const float* down_w1 = (const float*)d_in[10];
    const float* down_b1 = (const float*)d_in[11];
    const float* conv_w2 = (const float*)d_in[12];
    const float* conv_b2 = (const float*)d_in[13];
    const float* down_w2 = (const float*)d_in[14];
    const float* down_b2 = (const float*)d_in[15];
    const float* fc_w    = (const float*)d_in[16];
    const float* fc_b    = (const float*)d_in[17];
    float* out = (float*)d_out;

    __half *p_x1h, *p_x2h, *p_x3h, *p_fcwh;
    cudaGetSymbolAddress((void**)&p_x1h, g_x1h);
    cudaGetSymbolAddress((void**)&p_x2h, g_x2h);
    cudaGetSymbolAddress((void**)&p_x3h, g_x3h);
    cudaGetSymbolAddress((void**)&p_fcwh, g_fcwh);
    __half *wc0, *wd0, *wc1, *wd1, *wc2, *wd2;
    cudaGetSymbolAddress((void**)&wc0, g_wc0h);
    cudaGetSymbolAddress((void**)&wd0, g_wd0h);
    cudaGetSymbolAddress((void**)&wc1, g_wc1);
    cudaGetSymbolAddress((void**)&wd1, g_wd1);
    cudaGetSymbolAddress((void**)&wc2, g_wc2);
    cudaGetSymbolAddress((void**)&wd2, g_wd2);

    const int SM1 = 3 * (16384 + 128 * 128 + 16384) + 1024;  // NT=128
    const int SM2 = 3 * (16384 + 64 * 128 + 16384) + 1024;   // NT=64
    const int SMF = 80 * 128 + 128 * 128;
    cudaFuncSetAttribute(tcn0_mma_kernel,
                         cudaFuncAttributeMaxDynamicSharedMemorySize, T0_SMEM);
    cudaFuncSetAttribute(tcn_mma_kernel<128, 3, 512, 128>,
                         cudaFuncAttributeMaxDynamicSharedMemorySize, SM1);
    cudaFuncSetAttribute(tcn_mma_kernel<512, 9, 128, 64>,
                         cudaFuncAttributeMaxDynamicSharedMemorySize, SM2);
    cudaFuncSetAttribute(fc_mma_kernel,
                         cudaFuncAttributeMaxDynamicSharedMemorySize, SMF);

    // one fused setup launch (init + detect + out bias + weight prep + GCN h)
    k_setup<<<(Q6 + 255) / 256, 256>>>(eidx, fc_b, out,
                                       conv_w0, down_w0, conv_w1, down_w1,
                                       conv_w2, down_w2, fc_w, x, gcn_w);

    k_deg<<<(NEDGE / 4 + 255) / 256, 256>>>(eidx);
    k_scatter<<<(NEDGE / 2 + 255) / 256, 256>>>(eidx);

    tcn0_mma_kernel<<<NTOT / 64, 256, T0_SMEM>>>(
        gcn_b, wc0, wd0, conv_b0, down_b0, p_x1h);
    tcn_mma_kernel<128, 3, 512, 128><<<dim3(NTOT / 128, 4), 256, SM1>>>(
        p_x1h, wc1, wd1, conv_b1, down_b1, p_x2h);
    tcn_mma_kernel<512, 9, 128, 64><<<dim3(NTOT / 64, 1), 256, SM2>>>(
        p_x2h, wc2, wd2, conv_b2, down_b2, p_x3h);

    fc_mma_kernel<<<dim3(BATCH / 128, FCF / FC_KSEG), 320, SMF>>>(p_x3h, p_fcwh, out);
}